// round 13
// baseline (speedup 1.0000x reference)
#include <cuda_runtime.h>
#include <cuda_fp16.h>
#include <cstdint>

// Problem constants
constexpr int Bb = 2;
constexpr int Tt = 2048;
constexpr int Cc = 1024;
constexpr int Hh = 16;
constexpr int Dd = 64;
constexpr int Mrows = Bb * Tt;        // 4096
constexpr int N3C = 3 * Cc;           // 3072

// Scratch (static device memory), fp16 packed (uint32 = 2 halves)
__device__ uint32_t g_xh[Mrows * Cc / 2];
__device__ uint32_t g_wah[Cc * N3C / 2];
__device__ uint32_t g_wph[Cc * Cc / 2];
__device__ uint32_t g_yh[Mrows * Cc / 2];
__device__ uint32_t g_qh[Bb * Hh * Tt * 32];
__device__ uint32_t g_kh[Bb * Hh * Tt * 32];
__device__ uint32_t g_vh[Bb * Hh * Tt * 32];
__device__ float g_cos[Tt * (Dd / 2)];
__device__ float g_sin[Tt * (Dd / 2)];

__device__ __forceinline__ uint32_t packhf(float lo, float hi) {
    uint32_t r; asm("cvt.rn.f16x2.f32 %0, %1, %2;" : "=r"(r) : "f"(hi), "f"(lo));
    return r;
}
__device__ __forceinline__ uint32_t ex2_h2(uint32_t x) {
    uint32_t r; asm("ex2.approx.f16x2 %0, %1;" : "=r"(r) : "r"(x)); return r;
}
__device__ __forceinline__ void mma_f16(float* c, const uint32_t* a, const uint32_t* b) {
    asm volatile(
        "mma.sync.aligned.m16n8k16.row.col.f32.f16.f16.f32 "
        "{%0,%1,%2,%3}, {%4,%5,%6,%7}, {%8,%9}, {%0,%1,%2,%3};"
        : "+f"(c[0]), "+f"(c[1]), "+f"(c[2]), "+f"(c[3])
        : "r"(a[0]), "r"(a[1]), "r"(a[2]), "r"(a[3]), "r"(b[0]), "r"(b[1]));
}
// f16-accumulator variant: d/c are 2 packed f16x2 regs
__device__ __forceinline__ void mma_f16_d16(uint32_t* d, const uint32_t* a, const uint32_t* b) {
    asm volatile(
        "mma.sync.aligned.m16n8k16.row.col.f16.f16.f16.f16 "
        "{%0,%1}, {%2,%3,%4,%5}, {%6,%7}, {%0,%1};"
        : "+r"(d[0]), "+r"(d[1])
        : "r"(a[0]), "r"(a[1]), "r"(a[2]), "r"(a[3]), "r"(b[0]), "r"(b[1]));
}

#define LDSM_X4(r0, r1, r2, r3, addr) \
    asm volatile("ldmatrix.sync.aligned.m8n8.x4.shared.b16 {%0,%1,%2,%3}, [%4];" \
                 : "=r"(r0), "=r"(r1), "=r"(r2), "=r"(r3) : "r"(addr))
#define LDSM_X4_T(r0, r1, r2, r3, addr) \
    asm volatile("ldmatrix.sync.aligned.m8n8.x4.trans.shared.b16 {%0,%1,%2,%3}, [%4];" \
                 : "=r"(r0), "=r"(r1), "=r"(r2), "=r"(r3) : "r"(addr))
#define CP_ASYNC16(dst, src) \
    asm volatile("cp.async.cg.shared.global [%0], [%1], 16;" :: "r"(dst), "l"(src))
#define CP_COMMIT() asm volatile("cp.async.commit_group;" ::: "memory")
#define CP_WAIT(n)  asm volatile("cp.async.wait_group %0;" :: "n"(n) : "memory")

__device__ __forceinline__ uint32_t smaddr(const void* p) {
    return (uint32_t)__cvta_generic_to_shared(p);
}
__device__ __forceinline__ uint32_t hadd2u(uint32_t a, uint32_t b) {
    uint32_t r; asm("add.f16x2 %0, %1, %2;" : "=r"(r) : "r"(a), "r"(b)); return r;
}

// ---------------------------------------------------------------------------
// Fused setup kernel: f32->f16 converts (x, w_attn, w_proj) + RoPE table
// ---------------------------------------------------------------------------
constexpr int NX2 = Mrows * Cc / 2;
constexpr int NWA2 = Cc * N3C / 2;
constexpr int NWP2 = Cc * Cc / 2;
constexpr int NROPE = Tt * (Dd / 2);
constexpr int NSETUP = NX2 + NWA2 + NWP2 + NROPE;

__global__ void setup_kernel(const float* __restrict__ x,
                             const float* __restrict__ wa,
                             const float* __restrict__ wp) {
    int i = blockIdx.x * blockDim.x + threadIdx.x;
    if (i < NX2) {
        float2 v = ((const float2*)x)[i];
        g_xh[i] = packhf(v.x, v.y);
    } else if (i < NX2 + NWA2) {
        int off = i - NX2;
        float2 v = ((const float2*)wa)[off];
        g_wah[off] = packhf(v.x, v.y);
    } else if (i < NX2 + NWA2 + NWP2) {
        int off = i - NX2 - NWA2;
        float2 v = ((const float2*)wp)[off];
        g_wph[off] = packhf(v.x, v.y);
    } else if (i < NSETUP) {
        int idx = i - NX2 - NWA2 - NWP2;
        int t = idx / (Dd / 2);
        int p = idx % (Dd / 2);
        double inv = exp(-((double)(2 * p) / (double)Dd) * log(10000.0));
        float ang = (float)((double)t * inv);
        g_cos[idx] = cosf(ang);
        g_sin[idx] = sinf(ang);
    }
}

// ---------------------------------------------------------------------------
// F16 mma.sync GEMM (R12 verified): CTA 128x128, BK=64, 3-stage ring,
// ldmatrix, single barrier/iter, 2 CTAs/SM.
// ---------------------------------------------------------------------------
constexpr int AP2 = 72;
constexpr int BP2 = 136;
constexpr int HSTAGE = 128 * AP2 + 64 * BP2;
constexpr int HGEMM_SMEM = 3 * HSTAGE * 2;

__global__ __launch_bounds__(256, 2) void hgemm_kernel(
    const __half* __restrict__ Ah, const __half* __restrict__ Bh,
    const float* __restrict__ bias, float* __restrict__ out,
    int M, int N, int K, int mode)
{
    extern __shared__ __half sm[];

    const int tid = threadIdx.x;
    const int lane = tid & 31;
    const int wid = tid >> 5;
    const int wm = wid >> 2;
    const int wn = wid & 3;
    const int mBase = blockIdx.y * 128;
    const int nBase = blockIdx.x * 128;
    const int g4 = lane >> 2;
    const int c4 = lane & 3;

    float acc[4][4][4] = {};

    auto prefetch = [&](int it) {
        const int k0 = it * 64;
        __half* As = sm + (it % 3) * HSTAGE;
        __half* Bs = As + 128 * AP2;
#pragma unroll
        for (int p = 0; p < 4; p++) {
            int id = p * 256 + tid;
            int r = id >> 3, ch = id & 7;
            CP_ASYNC16(smaddr(&As[r * AP2 + ch * 8]),
                       Ah + (size_t)(mBase + r) * K + k0 + ch * 8);
        }
#pragma unroll
        for (int p = 0; p < 4; p++) {
            int id = p * 256 + tid;
            int r = id >> 4, ch = id & 15;
            CP_ASYNC16(smaddr(&Bs[r * BP2 + ch * 8]),
                       Bh + (size_t)(k0 + r) * N + nBase + ch * 8);
        }
        CP_COMMIT();
    };

    const int KT = K / 64;
    prefetch(0);
    prefetch(1);

    for (int it = 0; it < KT; it++) {
        CP_WAIT(1);
        __syncthreads();
        if (it + 2 < KT) prefetch(it + 2);
        else CP_COMMIT();

        const __half* As = sm + (it % 3) * HSTAGE;
        const __half* Bs = As + 128 * AP2;

#pragma unroll
        for (int kc = 0; kc < 4; kc++) {
            uint32_t bf[2][4];
#pragma unroll
            for (int nb = 0; nb < 2; nb++) {
                uint32_t a = smaddr(&Bs[(kc * 16 + (lane & 15)) * BP2 +
                                        wn * 32 + nb * 16 + (lane >> 4) * 8]);
                LDSM_X4_T(bf[nb][0], bf[nb][1], bf[nb][2], bf[nb][3], a);
            }
            uint32_t af[4][4];
#pragma unroll
            for (int mt = 0; mt < 4; mt++) {
                uint32_t a = smaddr(&As[(wm * 64 + mt * 16 + (lane & 15)) * AP2 +
                                        kc * 16 + (lane >> 4) * 8]);
                LDSM_X4(af[mt][0], af[mt][1], af[mt][2], af[mt][3], a);
            }
#pragma unroll
            for (int mt = 0; mt < 4; mt++)
#pragma unroll
                for (int nb = 0; nb < 2; nb++) {
                    mma_f16(acc[mt][nb * 2],     af[mt], &bf[nb][0]);
                    mma_f16(acc[mt][nb * 2 + 1], af[mt], &bf[nb][2]);
                }
        }
    }

    // Epilogue
#pragma unroll
    for (int mt = 0; mt < 4; mt++) {
#pragma unroll
        for (int nt = 0; nt < 4; nt++) {
            const int col = nBase + wn * 32 + nt * 8 + 2 * c4;
            const float b0 = __ldg(&bias[col]);
            const float b1 = __ldg(&bias[col + 1]);
            const int row0 = mBase + wm * 64 + mt * 16 + g4;

            float v00 = acc[mt][nt][0] + b0, v01 = acc[mt][nt][1] + b1;
            float v10 = acc[mt][nt][2] + b0, v11 = acc[mt][nt][3] + b1;

            if (mode == 0) {
                *(float2*)(out + (size_t)row0 * N + col) = make_float2(v00, v01);
                *(float2*)(out + (size_t)(row0 + 8) * N + col) = make_float2(v10, v11);
            } else {
                const int part = col >> 10;          // 0=q 1=k 2=v
                const int h = (col & 1023) >> 6;
                const int d = col & 63;
                const int i = d >> 1;
                const int b = row0 >> 11;
                const int t0 = row0 & (Tt - 1);
                const int t1 = (row0 + 8) & (Tt - 1);
                if (part < 2) {
                    float co0 = g_cos[t0 * 32 + i], si0 = g_sin[t0 * 32 + i];
                    float co1 = g_cos[t1 * 32 + i], si1 = g_sin[t1 * 32 + i];
                    float r00 = v00 * co0 - v01 * si0;
                    float r01 = v01 * co0 + v00 * si0;
                    float r10 = v10 * co1 - v11 * si1;
                    float r11 = v11 * co1 + v10 * si1;
                    v00 = r00; v01 = r01; v10 = r10; v11 = r11;
                }
                if (part == 0) {   // fold log2(e)/sqrt(D) into Q (exp2 domain)
                    const float qs = 0.18033688011111366f;
                    v00 *= qs; v01 *= qs; v10 *= qs; v11 *= qs;
                }
                uint32_t* dst = (part == 0) ? g_qh : (part == 1) ? g_kh : g_vh;
                size_t base = ((size_t)(b * Hh + h)) * Tt;
                dst[(base + t0) * 32 + (d >> 1)] = packhf(v00, v01);
                dst[(base + t1) * 32 + (d >> 1)] = packhf(v10, v11);
            }
        }
    }
}

// ---------------------------------------------------------------------------
// Flash attention (causal), fp16 mma + ldmatrix, 3-stage ring.
// QK uses f16-ACCUMULATOR MMA (S pre-packed as f16x2; no packhf, packed mask).
// Row sums: pa fragments pre-summed with HADD2 -> ONE ones-MMA per tile.
// ---------------------------------------------------------------------------
constexpr int KP = 72;
constexpr int STAGE_H = 2 * 64 * KP;
constexpr int FLASH_SMEM = 3 * STAGE_H * 2;

__global__ __launch_bounds__(256) void flash_f16_kernel(
    const uint32_t* __restrict__ Qh, const uint32_t* __restrict__ Kh,
    const uint32_t* __restrict__ Vh, uint32_t* __restrict__ Yh)
{
    extern __shared__ __half smf[];

    const int tid = threadIdx.x;
    const int lane = tid & 31;
    const int w = tid >> 5;
    const int g4 = lane >> 2;
    const int c4 = lane & 3;

    const int cta = blockIdx.x;
    const int bh = cta & 31;
    const int qb = (Tt / 128 - 1) - (cta >> 5);
    const int m0 = qb << 7;

    const int wRow0 = m0 + w * 16;
    const int qr0 = wRow0 + g4;
    const int qr1 = qr0 + 8;

    const uint32_t* Qb = Qh + (size_t)bh * Tt * 32;
    const uint32_t* Kb = Kh + (size_t)bh * Tt * 32;
    const uint32_t* Vb = Vh + (size_t)bh * Tt * 32;

    uint32_t qf[4][4];
    {
        const uint32_t* q0 = Qb + (size_t)qr0 * 32;
        const uint32_t* q1 = Qb + (size_t)qr1 * 32;
#pragma unroll
        for (int kc = 0; kc < 4; kc++) {
            qf[kc][0] = q0[kc * 8 + c4];
            qf[kc][1] = q1[kc * 8 + c4];
            qf[kc][2] = q0[kc * 8 + c4 + 4];
            qf[kc][3] = q1[kc * 8 + c4 + 4];
        }
    }

    float o[8][4] = {};
    float osum[4] = {};

    const int ntiles = (m0 + 128) / 64;
    const uint32_t ones2[2] = {0x3C003C00u, 0x3C003C00u};

    // packed masking constants
    const __half2 qr0h = __floats2half2_rn((float)qr0, (float)qr0);
    const __half2 qr1h = __floats2half2_rn((float)qr1, (float)qr1);
    const __half2 bigh = __floats2half2_rn(65504.f, 65504.f);

    auto prefetch = [&](int it) {
        const int j0 = it * 64;
        __half* Ks = smf + (it % 3) * STAGE_H;
        __half* Vs = Ks + 64 * KP;
#pragma unroll
        for (int p = 0; p < 2; p++) {
            int id = p * 256 + tid;
            int r = id >> 3, ch = id & 7;
            CP_ASYNC16(smaddr(&Ks[r * KP + ch * 8]),
                       (const char*)(Kb + (size_t)(j0 + r) * 32 + ch * 4));
            CP_ASYNC16(smaddr(&Vs[r * KP + ch * 8]),
                       (const char*)(Vb + (size_t)(j0 + r) * 32 + ch * 4));
        }
        CP_COMMIT();
    };

    prefetch(0);
    if (1 < ntiles) prefetch(1); else CP_COMMIT();

    for (int it = 0; it < ntiles; it++) {
        const int j0 = it * 64;
        __half* Ks = smf + (it % 3) * STAGE_H;
        __half* Vs = Ks + 64 * KP;

        CP_WAIT(1);
        __syncthreads();
        if (it + 2 < ntiles) prefetch(it + 2);
        else CP_COMMIT();

        if (j0 <= wRow0 + 15) {
            // ---- S = Q @ K^T  (f16 accumulators, packed) ----
            uint32_t sh[8][2] = {};
#pragma unroll
            for (int ntp = 0; ntp < 4; ntp++) {
                const int nt0 = 2 * ntp, nt1 = nt0 + 1;
                uint32_t kb0[8], kb1[8];
                uint32_t a00 = smaddr(&Ks[(nt0 * 8 + (lane & 7)) * KP + ((lane >> 3) & 3) * 8]);
                LDSM_X4(kb0[0], kb0[1], kb0[2], kb0[3], a00);
                uint32_t a01 = smaddr(&Ks[(nt0 * 8 + (lane & 7)) * KP + 32 + ((lane >> 3) & 3) * 8]);
                LDSM_X4(kb0[4], kb0[5], kb0[6], kb0[7], a01);
                uint32_t a10 = smaddr(&Ks[(nt1 * 8 + (lane & 7)) * KP + ((lane >> 3) & 3) * 8]);
                LDSM_X4(kb1[0], kb1[1], kb1[2], kb1[3], a10);
                uint32_t a11 = smaddr(&Ks[(nt1 * 8 + (lane & 7)) * KP + 32 + ((lane >> 3) & 3) * 8]);
                LDSM_X4(kb1[4], kb1[5], kb1[6], kb1[7], a11);
#pragma unroll
                for (int kc = 0; kc < 4; kc++) {
                    mma_f16_d16(sh[nt0], qf[kc], &kb0[kc * 2]);
                    mma_f16_d16(sh[nt1], qf[kc], &kb1[kc * 2]);
                }
            }

            // ---- causal mask, packed (boundary tiles only) ----
            if (j0 + 63 > wRow0) {
#pragma unroll
                for (int nt = 0; nt < 8; nt++) {
                    float cb = (float)(j0 + nt * 8 + 2 * c4);
                    __half2 colh = __floats2half2_rn(cb, cb + 1.f);
                    __half2 s0 = *(__half2*)&sh[nt][0];
                    __half2 s1 = *(__half2*)&sh[nt][1];
                    s0 = __hsub2(s0, __hmul2(__hgt2(colh, qr0h), bigh));
                    s1 = __hsub2(s1, __hmul2(__hgt2(colh, qr1h), bigh));
                    sh[nt][0] = *(uint32_t*)&s0;
                    sh[nt][1] = *(uint32_t*)&s1;
                }
            }

            // ---- p = exp2(s), already packed ----
            uint32_t pa[4][4];
#pragma unroll
            for (int kcb = 0; kcb < 4; kcb++) {
                pa[kcb][0] = ex2_h2(sh[2 * kcb][0]);
                pa[kcb][1] = ex2_h2(sh[2 * kcb][1]);
                pa[kcb][2] = ex2_h2(sh[2 * kcb + 1][0]);
                pa[kcb][3] = ex2_h2(sh[2 * kcb + 1][1]);
            }

            // ---- row sums: pre-sum pa fragments, single ones-MMA ----
            uint32_t ps[4];
#pragma unroll
            for (int r = 0; r < 4; r++)
                ps[r] = hadd2u(hadd2u(pa[0][r], pa[1][r]),
                               hadd2u(pa[2][r], pa[3][r]));
            mma_f16(osum, ps, ones2);

            // ---- O += P @ V ----
#pragma unroll
            for (int kcb = 0; kcb < 4; kcb++) {
#pragma unroll
                for (int dbp = 0; dbp < 2; dbp++) {
                    const int db0 = 2 * dbp, db1 = db0 + 1;
                    uint32_t vb0[4], vb1[4];
                    uint32_t va0 = smaddr(&Vs[(kcb * 16 + (lane & 15)) * KP +
                                              db0 * 16 + (lane >> 4) * 8]);
                    LDSM_X4_T(vb0[0], vb0[1], vb0[2], vb0[3], va0);
                    uint32_t va1 = smaddr(&Vs[(kcb * 16 + (lane & 15)) * KP +
                                              db1 * 16 + (lane >> 4) * 8]);
                    LDSM_X4_T(vb1[0], vb1[1], vb1[2], vb1[3], va1);
                    mma_f16(o[db0 * 2],     pa[kcb], &vb0[0]);
                    mma_f16(o[db1 * 2],     pa[kcb], &vb1[0]);
                    mma_f16(o[db0 * 2 + 1], pa[kcb], &vb0[2]);
                    mma_f16(o[db1 * 2 + 1], pa[kcb], &vb1[2]);
                }
            }
        }
    }

    const float inv0 = 1.f / osum[0];
    const float inv1 = 1.f / osum[2];
    const int b = bh >> 4;
    const int h = bh & 15;
    uint32_t* y0 = Yh + ((size_t)(b * Tt + qr0)) * (Cc / 2) + h * 32;
    uint32_t* y1 = Yh + ((size_t)(b * Tt + qr1)) * (Cc / 2) + h * 32;
#pragma unroll
    for (int nt = 0; nt < 8; nt++) {
        int dw = (nt * 8 + 2 * c4) >> 1;
        y0[dw] = packhf(o[nt][0] * inv0, o[nt][1] * inv0);
        y1[dw] = packhf(o[nt][2] * inv1, o[nt][3] * inv1);
    }
}

// ---------------------------------------------------------------------------
// launch
// ---------------------------------------------------------------------------
extern "C" void kernel_launch(void* const* d_in, const int* in_sizes, int n_in,
                              void* d_out, int out_size) {
    const float* x      = (const float*)d_in[0];
    const float* w_attn = (const float*)d_in[1];
    const float* b_attn = (const float*)d_in[2];
    const float* w_proj = (const float*)d_in[3];
    const float* b_proj = (const float*)d_in[4];
    float* out = (float*)d_out;

    uint32_t *xh, *wah, *wph, *yh, *qh, *kh, *vh;
    cudaGetSymbolAddress((void**)&xh, g_xh);
    cudaGetSymbolAddress((void**)&wah, g_wah);
    cudaGetSymbolAddress((void**)&wph, g_wph);
    cudaGetSymbolAddress((void**)&yh, g_yh);
    cudaGetSymbolAddress((void**)&qh, g_qh);
    cudaGetSymbolAddress((void**)&kh, g_kh);
    cudaGetSymbolAddress((void**)&vh, g_vh);

    cudaFuncSetAttribute(flash_f16_kernel,
                         cudaFuncAttributeMaxDynamicSharedMemorySize, FLASH_SMEM);
    cudaFuncSetAttribute(hgemm_kernel,
                         cudaFuncAttributeMaxDynamicSharedMemorySize, HGEMM_SMEM);

    // Fused converts + RoPE table
    setup_kernel<<<(NSETUP + 255) / 256, 256>>>(x, w_attn, w_proj);

    // QKV GEMM (f16 mma) + fused bias + RoPE + head scatter
    hgemm_kernel<<<dim3(N3C / 128, Mrows / 128), 256, HGEMM_SMEM>>>(
        (const __half*)xh, (const __half*)wah, b_attn, nullptr, Mrows, N3C, Cc, 1);
    // Flash attention (fp16 mma, f16-accum QK, constant-shift softmax)
    flash_f16_kernel<<<(Tt / 128) * Bb * Hh, 256, FLASH_SMEM>>>(qh, kh, vh, yh);
    // Output projection (f16 mma) + fused bias, fp32 out
    hgemm_kernel<<<dim3(Cc / 128, Mrows / 128), 256, HGEMM_SMEM>>>(
        (const __half*)yh, (const __half*)wph, b_proj, out, Mrows, Cc, Cc, 0);
}